// round 15
// baseline (speedup 1.0000x reference)
#include <cuda_runtime.h>
#include <cstdint>

#define NS      65536
#define HALF    32
#define NHID    512
#define NOUT    736
#define NOUTP   768
#define KB      8
#define TB      3.0f

#define BM      128
#define BN      64
#define BKB     128
#define NTHR    128
#define GPERS   296     // 2 CTAs/SM x 148 SMs

#define SAH     0
#define SAL     16384
#define SBH     32768
#define SBL     40960
#define STAGE   49152
#define SMEM_TOTAL (2*STAGE)

// ================= static scratch =================
__device__ int8_t g_xq1h[(size_t)NS*128], g_xq1l[(size_t)NS*128];
__device__ float  g_xs1[NS];
__device__ int8_t g_xq2h[(size_t)NS*128], g_xq2l[(size_t)NS*128];
__device__ float  g_xs2[NS];
__device__ int8_t g_q0h[(size_t)NS*512],  g_q0l[(size_t)NS*512];
__device__ float  g_s0[NS];
__device__ float  g_act[(size_t)NS*512];
__device__ float  g_bufC[(size_t)NS*NOUTP];
__device__ int8_t g_w1h[2][512*128], g_w1l[2][512*128];
__device__ int8_t g_w2h[2][512*512], g_w2l[2][512*512];
__device__ int8_t g_w3h[2][512*512], g_w3l[2][512*512];
__device__ int8_t g_w4h[2][768*512], g_w4l[2][768*512];
__device__ float  g_ws1[2][512], g_ws2[2][512], g_ws3[2][512], g_ws4[2][768];
__device__ float  g_b4p[2][768];

// ================= helpers =================
__device__ __forceinline__ uint32_t smem_u32(const void* p) {
    uint32_t a;
    asm("{ .reg .u64 t; cvta.to.shared.u64 t, %1; cvt.u32.u64 %0, t; }" : "=r"(a) : "l"(p));
    return a;
}
#define SWZ(x) ((x) ^ (((x) >> 3) & 0x70))

#define CP16(dst, src) asm volatile("cp.async.cg.shared.global [%0], [%1], 16;" :: "r"(dst), "l"(src))
#define CP_COMMIT()    asm volatile("cp.async.commit_group;" ::: "memory")
#define CP_WAIT(N)     asm volatile("cp.async.wait_group %0;" :: "n"(N) : "memory")

#define LDSM4(r, a) \
    asm volatile("ldmatrix.sync.aligned.m8n8.x4.shared.b16 {%0,%1,%2,%3}, [%4];" \
        : "=r"((r)[0]), "=r"((r)[1]), "=r"((r)[2]), "=r"((r)[3]) : "r"(a))

#define MMAI8(c, a, b0, b1) \
    asm volatile("mma.sync.aligned.m16n8k32.row.col.s32.s8.s8.s32 " \
        "{%0,%1,%2,%3}, {%4,%5,%6,%7}, {%8,%9}, {%0,%1,%2,%3};" \
        : "+r"((c)[0]), "+r"((c)[1]), "+r"((c)[2]), "+r"((c)[3]) \
        : "r"((a)[0]), "r"((a)[1]), "r"((a)[2]), "r"((a)[3]), "r"(b0), "r"(b1))

// ================= persistent int8 split GEMM =================
// C[M,N] = act( sa[m]*sb[n]*(16384*ACC_hh + 128*ACC_mix) + bias[n] )
// 128x64 tile, 4 warps (2x2, 64x32), BKB=128, 2-stage ring continuous across tiles.
template <int KT, int ACT>
__global__ void __launch_bounds__(NTHR, 2) gemm_i8(
    const int8_t* __restrict__ Aq, const int8_t* __restrict__ Aql,
    const float* __restrict__ sA,
    const int8_t* __restrict__ Bq, const int8_t* __restrict__ Bql,
    const float* __restrict__ sB,
    const float* __restrict__ bias,
    float* __restrict__ C, int ldc,
    int ncol, int ntiles)
{
    extern __shared__ __align__(1024) char smem[];
    const uint32_t sb_ = smem_u32(smem);
    const int tid  = threadIdx.x;
    const int wid  = tid >> 5;
    const int l    = tid & 31;
    const int wm   = wid & 1;
    const int wn   = wid >> 1;
    const int bid  = blockIdx.x;
    const int G    = gridDim.x;
    const int lda  = KT * BKB;

    if (bid >= ntiles) return;
    const int ntile_cta = (ntiles - 1 - bid) / G + 1;
    const int P = ntile_cta * KT;

    int acc1[4][4][4], acc2[4][4][4];
#pragma unroll
    for (int i = 0; i < 4; i++)
#pragma unroll
        for (int j = 0; j < 4; j++)
#pragma unroll
            for (int q = 0; q < 4; q++) { acc1[i][j][q] = 0; acc2[i][j][q] = 0; }

    auto load_p = [&](int p) {
        const int it  = p / KT;
        const int kt  = p % KT;
        const int t   = bid + it * G;
        const int m   = t / ncol;
        const int n   = t - m * ncol;
        const int row0 = m * BM;
        const int col0 = n * BN;
        const uint32_t sbase = sb_ + (p & 1) * STAGE;
        const int koff = kt * BKB;
#pragma unroll
        for (int i = 0; i < 8; i++) {
            int c = tid + i * NTHR;
            int r = c >> 3, q = c & 7;
            uint32_t off = SWZ(r * 128 + q * 16);
            const size_t ga = (size_t)(row0 + r) * lda + koff + q * 16;
            CP16(sbase + SAH + off, Aq + ga);
            CP16(sbase + SAL + off, Aql + ga);
        }
#pragma unroll
        for (int i = 0; i < 4; i++) {
            int c = tid + i * NTHR;
            int n2 = c >> 3, q = c & 7;
            uint32_t off = SWZ(n2 * 128 + q * 16);
            const size_t gb = (size_t)(col0 + n2) * lda + koff + q * 16;
            CP16(sbase + SBH + off, Bq + gb);
            CP16(sbase + SBL + off, Bql + gb);
        }
    };

    auto compute = [&](int s) {
        const uint32_t AHB = sb_ + s * STAGE + SAH;
        const uint32_t ALB = sb_ + s * STAGE + SAL;
        const uint32_t BHB = sb_ + s * STAGE + SBH;
        const uint32_t BLB = sb_ + s * STAGE + SBL;
#pragma unroll
        for (int ksl = 0; ksl < 4; ksl++) {
            uint32_t ah[4][4], al[4][4], bh[2][4], bl[2][4];
#pragma unroll
            for (int j16 = 0; j16 < 2; j16++) {
                int n = wn * 32 + j16 * 16 + (l & 7) + ((l >> 4) << 3);
                int colb = ksl * 32 + ((l >> 3) & 1) * 16;
                uint32_t sw = (uint32_t)((n & 7) << 4);
                LDSM4(bh[j16], BHB + n * 128 + (colb ^ sw));
                LDSM4(bl[j16], BLB + n * 128 + (colb ^ sw));
            }
#pragma unroll
            for (int i = 0; i < 4; i++) {
                int row = wm * 64 + i * 16 + (l & 15);
                int colb = ksl * 32 + (l >> 4) * 16;
                uint32_t sw = (uint32_t)((row & 7) << 4);
                LDSM4(ah[i], AHB + row * 128 + (colb ^ sw));
                LDSM4(al[i], ALB + row * 128 + (colb ^ sw));
            }
#pragma unroll
            for (int i = 0; i < 4; i++)
#pragma unroll
                for (int j16 = 0; j16 < 2; j16++)
#pragma unroll
                    for (int hf = 0; hf < 2; hf++)
                        MMAI8(acc1[i][j16 * 2 + hf], ah[i], bh[j16][hf*2], bh[j16][hf*2+1]);
#pragma unroll
            for (int i = 0; i < 4; i++)
#pragma unroll
                for (int j16 = 0; j16 < 2; j16++)
#pragma unroll
                    for (int hf = 0; hf < 2; hf++)
                        MMAI8(acc2[i][j16 * 2 + hf], ah[i], bl[j16][hf*2], bl[j16][hf*2+1]);
#pragma unroll
            for (int i = 0; i < 4; i++)
#pragma unroll
                for (int j16 = 0; j16 < 2; j16++)
#pragma unroll
                    for (int hf = 0; hf < 2; hf++)
                        MMAI8(acc2[i][j16 * 2 + hf], al[i], bh[j16][hf*2], bh[j16][hf*2+1]);
        }
    };

    load_p(0); CP_COMMIT();
    for (int p = 0; p < P; p++) {
        CP_WAIT(0);
        __syncthreads();
        if (p + 1 < P) { load_p(p + 1); CP_COMMIT(); }
        compute(p & 1);

        if (p % KT == KT - 1) {
            // epilogue for just-finished tile
            const int t = bid + (p / KT) * G;
            const int m = t / ncol;
            const int n = t - m * ncol;
            const int row0 = m * BM;
            const int col0 = n * BN;
#pragma unroll
            for (int i = 0; i < 4; i++) {
                const int r0 = row0 + wm * 64 + i * 16 + (l >> 2);
                const float sa0 = sA[r0], sa1 = sA[r0 + 8];
#pragma unroll
                for (int j = 0; j < 4; j++) {
                    const int c = col0 + wn * 32 + j * 8 + (l & 3) * 2;
                    const float sb0 = sB[c], sb1 = sB[c + 1];
                    const float b0 = bias[c], b1 = bias[c + 1];
                    float f0 = fmaf((float)acc1[i][j][0], 16384.f, (float)acc2[i][j][0] * 128.f);
                    float f1 = fmaf((float)acc1[i][j][1], 16384.f, (float)acc2[i][j][1] * 128.f);
                    float f2 = fmaf((float)acc1[i][j][2], 16384.f, (float)acc2[i][j][2] * 128.f);
                    float f3 = fmaf((float)acc1[i][j][3], 16384.f, (float)acc2[i][j][3] * 128.f);
                    float v0 = fmaf(f0, sa0 * sb0, b0);
                    float v1 = fmaf(f1, sa0 * sb1, b1);
                    float v2 = fmaf(f2, sa1 * sb0, b0);
                    float v3 = fmaf(f3, sa1 * sb1, b1);
                    if (ACT) {
                        v0 = (v0 > 0.f) ? v0 : 0.2f * v0;
                        v1 = (v1 > 0.f) ? v1 : 0.2f * v1;
                        v2 = (v2 > 0.f) ? v2 : 0.2f * v2;
                        v3 = (v3 > 0.f) ? v3 : 0.2f * v3;
                    }
                    *(float2*)(C + (size_t)r0 * ldc + c)       = make_float2(v0, v1);
                    *(float2*)(C + (size_t)(r0 + 8) * ldc + c) = make_float2(v2, v3);
                    acc1[i][j][0] = 0; acc1[i][j][1] = 0; acc1[i][j][2] = 0; acc1[i][j][3] = 0;
                    acc2[i][j][0] = 0; acc2[i][j][1] = 0; acc2[i][j][2] = 0; acc2[i][j][3] = 0;
                }
            }
        }
    }
}

// ================= quant helpers =================
__device__ __forceinline__ void quant1(float v, float inv, float sa128,
                                       int8_t& h8, int8_t& l8) {
    int h = __float2int_rn(v * inv * (1.f / 128.f));
    float r = fmaf(-(float)h, sa128, v);
    int lo = __float2int_rn(r * inv);
    h8 = (int8_t)h; l8 = (int8_t)lo;
}

template <int NG>
__global__ void qact(const float* __restrict__ in, int inld, int ncols,
                     int8_t* __restrict__ qh, int8_t* __restrict__ ql,
                     float* __restrict__ scale)
{
    const int warp = (blockIdx.x * blockDim.x + threadIdx.x) >> 5;
    const int lane = threadIdx.x & 31;
    if (warp >= NS) return;
    const float* rp = in + (size_t)warp * inld;
    float4 v[NG];
    float amax = 0.f;
#pragma unroll
    for (int g = 0; g < NG; g++) {
        int c = g * 128 + lane * 4;
        v[g] = (c < ncols) ? *(const float4*)(rp + c) : make_float4(0.f, 0.f, 0.f, 0.f);
        amax = fmaxf(amax, fmaxf(fmaxf(fabsf(v[g].x), fabsf(v[g].y)),
                                 fmaxf(fabsf(v[g].z), fabsf(v[g].w))));
    }
#pragma unroll
    for (int off = 16; off > 0; off >>= 1)
        amax = fmaxf(amax, __shfl_xor_sync(0xffffffffu, amax, off));
    amax = fmaxf(amax, 1e-20f);
    const float sa    = amax * (1.f / 16256.f);
    const float inv   = 16256.f / amax;
    const float sa128 = sa * 128.f;
    const size_t base = (size_t)warp * (NG * 128);
#pragma unroll
    for (int g = 0; g < NG; g++) {
        int c = g * 128 + lane * 4;
        char4 h4, l4;
        quant1(v[g].x, inv, sa128, (int8_t&)h4.x, (int8_t&)l4.x);
        quant1(v[g].y, inv, sa128, (int8_t&)h4.y, (int8_t&)l4.y);
        quant1(v[g].z, inv, sa128, (int8_t&)h4.z, (int8_t&)l4.z);
        quant1(v[g].w, inv, sa128, (int8_t&)h4.w, (int8_t&)l4.w);
        *(char4*)(qh + base + c) = h4;
        *(char4*)(ql + base + c) = l4;
    }
    if (lane == 0) scale[warp] = sa;
}

// ================= merged prep =================
struct QWArgs {
    const float* W[8];
    const float* b4[2];
    int8_t* H[8];
    int8_t* L8[8];
    float*  S[8];
    float*  bp[2];
};

__global__ void prep_all(QWArgs a, const float* __restrict__ x,
                         int8_t* __restrict__ xqh, int8_t* __restrict__ xql,
                         float* __restrict__ xs)
{
    int gw = (int)((blockIdx.x * blockDim.x + threadIdx.x) >> 5);
    const int lane = threadIdx.x & 31;

    if (gw < NS) {
        const float* rp = x + (size_t)gw * 64;
        int c = lane * 4;
        float4 v = (c < HALF) ? *(const float4*)(rp + c) : make_float4(0.f, 0.f, 0.f, 0.f);
        float amax = fmaxf(fmaxf(fabsf(v.x), fabsf(v.y)), fmaxf(fabsf(v.z), fabsf(v.w)));
#pragma unroll
        for (int off = 16; off > 0; off >>= 1)
            amax = fmaxf(amax, __shfl_xor_sync(0xffffffffu, amax, off));
        amax = fmaxf(amax, 1e-20f);
        const float sa    = amax * (1.f / 16256.f);
        const float inv   = 16256.f / amax;
        const float sa128 = sa * 128.f;
        char4 h4, l4;
        quant1(v.x, inv, sa128, (int8_t&)h4.x, (int8_t&)l4.x);
        quant1(v.y, inv, sa128, (int8_t&)h4.y, (int8_t&)l4.y);
        quant1(v.z, inv, sa128, (int8_t&)h4.z, (int8_t&)l4.z);
        quant1(v.w, inv, sa128, (int8_t&)h4.w, (int8_t&)l4.w);
        const size_t base = (size_t)gw * 128 + c;
        *(char4*)(xqh + base) = h4;
        *(char4*)(xql + base) = l4;
        if (lane == 0) xs[gw] = sa;
        return;
    }
    gw -= NS;
    if (gw >= 4608) return;
    const int cc = (gw >= 2304) ? 1 : 0;
    int off = gw - cc * 2304;
    int seg, n, K, N, Kpad;
    if (off < 512)       { seg = 0; n = off;        K = 32;  N = 512; Kpad = 128; }
    else if (off < 1024) { seg = 1; n = off - 512;  K = 512; N = 512; Kpad = 512; }
    else if (off < 1536) { seg = 2; n = off - 1024; K = 512; N = 512; Kpad = 512; }
    else                 { seg = 3; n = off - 1536; K = 512; N = 736; Kpad = 512; }
    const int widx = cc * 4 + seg;
    const float* W = a.W[widx];
    const int nk = Kpad >> 5;

    float vals[16];
    float amax = 0.f;
#pragma unroll 16
    for (int i = 0; i < 16; i++) {
        if (i < nk) {
            int k = lane + 32 * i;
            float v = (k < K && n < N) ? W[(size_t)k * N + n] : 0.f;
            vals[i] = v;
            amax = fmaxf(amax, fabsf(v));
        }
    }
#pragma unroll
    for (int o = 16; o > 0; o >>= 1)
        amax = fmaxf(amax, __shfl_xor_sync(0xffffffffu, amax, o));
    amax = fmaxf(amax, 1e-20f);
    const float sbv   = amax * (1.f / 16256.f);
    const float inv   = 16256.f / amax;
    const float sb128 = sbv * 128.f;
    const size_t base = (size_t)n * Kpad;
#pragma unroll 16
    for (int i = 0; i < 16; i++) {
        if (i < nk) {
            int k = lane + 32 * i;
            int8_t h8, l8;
            quant1(vals[i], inv, sb128, h8, l8);
            a.H[widx][base + k]  = h8;
            a.L8[widx][base + k] = l8;
        }
    }
    if (lane == 0) {
        a.S[widx][n] = sbv;
        if (seg == 3) a.bp[cc][n] = (n < 736) ? a.b4[cc][n] : 0.f;
    }
}

// ================= spline (identical numerics) =================
__device__ __forceinline__ float softplusf(float x) {
    return (x > 0.f) ? (x + log1pf(expf(-x))) : log1pf(expf(x));
}

__global__ void __launch_bounds__(256) spline_kernel(
    const float* __restrict__ y, int ldy,
    const float* __restrict__ cond,
    float* __restrict__ out_y, int ldo,
    float* __restrict__ logdet, int add,
    int8_t* __restrict__ qh, int8_t* __restrict__ ql, float* __restrict__ qs)
{
    const int gid = blockIdx.x * 256 + threadIdx.x;
    const int s   = gid >> 5;
    const int dim = gid & 31;
    if (s >= NS) return;

    const float* p = cond + (size_t)s * NOUTP + dim * 23;
    const float x = y[(size_t)s * ldy + dim];

    float rw[KB], rh[KB];
#pragma unroll
    for (int i = 0; i < KB; i++) rw[i] = p[i];
#pragma unroll
    for (int i = 0; i < KB; i++) rh[i] = p[KB + i];

    float cw[KB + 1], wid[KB];
    {
        float m = rw[0];
#pragma unroll
        for (int i = 1; i < KB; i++) m = fmaxf(m, rw[i]);
        float s1 = 0.f, e[KB];
#pragma unroll
        for (int i = 0; i < KB; i++) { e[i] = expf(rw[i] - m); s1 += e[i]; }
        float inv1 = 1.f / s1, Wv[KB];
#pragma unroll
        for (int i = 0; i < KB; i++) Wv[i] = 2.f * TB * e[i] * inv1;
        float m2 = Wv[0];
#pragma unroll
        for (int i = 1; i < KB; i++) m2 = fmaxf(m2, Wv[i]);
        float s2 = 0.f;
#pragma unroll
        for (int i = 0; i < KB; i++) { e[i] = expf(Wv[i] - m2); s2 += e[i]; }
        float inv2 = 1.f / s2;
        float run = 0.f;
        cw[0] = -TB;
#pragma unroll
        for (int i = 0; i < KB; i++) {
            float w = 0.001f + (1.f - 0.001f * KB) * e[i] * inv2;
            run += w;
            cw[i + 1] = 2.f * TB * run - TB;
        }
        cw[KB] = TB;
#pragma unroll
        for (int i = 0; i < KB; i++) wid[i] = cw[i + 1] - cw[i];
    }

    float ch[KB + 1], hei[KB];
    {
        float m = rh[0];
#pragma unroll
        for (int i = 1; i < KB; i++) m = fmaxf(m, rh[i]);
        float s1 = 0.f, e[KB];
#pragma unroll
        for (int i = 0; i < KB; i++) { e[i] = expf(rh[i] - m); s1 += e[i]; }
        float inv1 = 1.f / s1, Hv[KB];
#pragma unroll
        for (int i = 0; i < KB; i++) Hv[i] = 2.f * TB * e[i] * inv1;
        float m2 = Hv[0];
#pragma unroll
        for (int i = 1; i < KB; i++) m2 = fmaxf(m2, Hv[i]);
        float s2 = 0.f;
#pragma unroll
        for (int i = 0; i < KB; i++) { e[i] = expf(Hv[i] - m2); s2 += e[i]; }
        float inv2 = 1.f / s2;
        float run = 0.f;
        ch[0] = -TB;
#pragma unroll
        for (int i = 0; i < KB; i++) {
            float h = 0.001f + (1.f - 0.001f * KB) * e[i] * inv2;
            run += h;
            ch[i + 1] = 2.f * TB * run - TB;
        }
        ch[KB] = TB;
#pragma unroll
        for (int i = 0; i < KB; i++) hei[i] = ch[i + 1] - ch[i];
    }

    float der[KB + 1];
    {
        const float CONST = 0.5397432446f;
        der[0] = 0.001f + softplusf(CONST);
        der[KB] = der[0];
#pragma unroll
        for (int i = 0; i < KB - 1; i++)
            der[i + 1] = 0.001f + softplusf(softplusf(p[2 * KB + i]));
    }

    const bool inside = (x >= -TB) && (x <= TB);
    const float xc = fminf(fmaxf(x, -TB), TB);
    int cnt = 0;
#pragma unroll
    for (int j = 0; j <= KB; j++) {
        float ce = cw[j] + ((j == KB) ? 1e-6f : 0.f);
        cnt += (xc >= ce) ? 1 : 0;
    }
    int idx = min(max(cnt - 1, 0), KB - 1);

    float in_cw = 0.f, in_w = 1.f, in_ch = 0.f, in_h = 1.f, in_der = 1.f, in_der1 = 1.f;
#pragma unroll
    for (int j = 0; j < KB; j++) {
        if (j == idx) {
            in_cw = cw[j]; in_w = wid[j]; in_ch = ch[j]; in_h = hei[j];
            in_der = der[j]; in_der1 = der[j + 1];
        }
    }
    const float in_d = in_h / in_w;
    const float theta = (xc - in_cw) / in_w;
    const float t1mt  = theta * (1.f - theta);
    const float num   = in_h * (in_d * theta * theta + in_der * t1mt);
    const float den   = in_d + (in_der + in_der1 - 2.f * in_d) * t1mt;
    const float outv  = in_ch + num / den;
    const float omt   = 1.f - theta;
    const float dnum  = in_d * in_d * (in_der1 * theta * theta + 2.f * in_d * t1mt + in_der * omt * omt);
    float lad = logf(dnum) - 2.f * logf(den);

    const float fv = inside ? outv : x;
    out_y[(size_t)s * ldo + dim] = fv;
    lad = inside ? lad : 0.f;

    if (qh) {
        float amax = fabsf(fv);
#pragma unroll
        for (int off = 16; off > 0; off >>= 1)
            amax = fmaxf(amax, __shfl_xor_sync(0xffffffffu, amax, off));
        amax = fmaxf(amax, 1e-20f);
        const float sa    = amax * (1.f / 16256.f);
        const float inv   = 16256.f / amax;
        const float sa128 = sa * 128.f;
        int8_t h8, l8;
        quant1(fv, inv, sa128, h8, l8);
        const size_t base = (size_t)s * 128 + dim;
        qh[base] = h8;  ql[base] = l8;
        qh[base + 32] = 0; ql[base + 32] = 0;
        qh[base + 64] = 0; ql[base + 64] = 0;
        qh[base + 96] = 0; ql[base + 96] = 0;
        if (dim == 0) qs[s] = sa;
    }

#pragma unroll
    for (int off = 16; off > 0; off >>= 1)
        lad += __shfl_down_sync(0xffffffffu, lad, off);
    if (dim == 0) {
        if (add) logdet[s] += lad;
        else     logdet[s]  = lad;
    }
}

// ================= launch =================
extern "C" void kernel_launch(void* const* d_in, const int* in_sizes, int n_in,
                              void* d_out, int out_size)
{
    const float* x = (const float*)d_in[0];
    const float* w[2][4] = {{(const float*)d_in[1], (const float*)d_in[3], (const float*)d_in[5], (const float*)d_in[7]},
                            {(const float*)d_in[9], (const float*)d_in[11], (const float*)d_in[13], (const float*)d_in[15]}};
    const float* bb[2][4] = {{(const float*)d_in[2], (const float*)d_in[4], (const float*)d_in[6], (const float*)d_in[8]},
                             {(const float*)d_in[10], (const float*)d_in[12], (const float*)d_in[14], (const float*)d_in[16]}};

    float* out    = (float*)d_out;
    float* logdet = out + (size_t)NS * 64;

    int8_t *xq1h, *xq1l, *xq2h, *xq2l, *q0h, *q0l;
    float  *xs1, *xs2, *s0, *actF, *bufC, *b4p;
    int8_t *w1h, *w1l, *w2h, *w2l, *w3h, *w3l, *w4h, *w4l;
    float  *ws1, *ws2, *ws3, *ws4;
    cudaGetSymbolAddress((void**)&xq1h, g_xq1h); cudaGetSymbolAddress((void**)&xq1l, g_xq1l);
    cudaGetSymbolAddress((void**)&xs1, g_xs1);
    cudaGetSymbolAddress((void**)&xq2h, g_xq2h); cudaGetSymbolAddress((void**)&xq2l, g_xq2l);
    cudaGetSymbolAddress((void**)&xs2, g_xs2);
    cudaGetSymbolAddress((void**)&q0h, g_q0h);   cudaGetSymbolAddress((void**)&q0l, g_q0l);
    cudaGetSymbolAddress((void**)&s0, g_s0);
    cudaGetSymbolAddress((void**)&actF, g_act);
    cudaGetSymbolAddress((void**)&bufC, g_bufC);
    cudaGetSymbolAddress((void**)&w1h, g_w1h); cudaGetSymbolAddress((void**)&w1l, g_w1l);
    cudaGetSymbolAddress((void**)&w2h, g_w2h); cudaGetSymbolAddress((void**)&w2l, g_w2l);
    cudaGetSymbolAddress((void**)&w3h, g_w3h); cudaGetSymbolAddress((void**)&w3l, g_w3l);
    cudaGetSymbolAddress((void**)&w4h, g_w4h); cudaGetSymbolAddress((void**)&w4l, g_w4l);
    cudaGetSymbolAddress((void**)&ws1, g_ws1); cudaGetSymbolAddress((void**)&ws2, g_ws2);
    cudaGetSymbolAddress((void**)&ws3, g_ws3); cudaGetSymbolAddress((void**)&ws4, g_ws4);
    cudaGetSymbolAddress((void**)&b4p, g_b4p);

    cudaFuncSetAttribute(gemm_i8<1,1>, cudaFuncAttributeMaxDynamicSharedMemorySize, SMEM_TOTAL);
    cudaFuncSetAttribute(gemm_i8<4,1>, cudaFuncAttributeMaxDynamicSharedMemorySize, SMEM_TOTAL);
    cudaFuncSetAttribute(gemm_i8<4,0>, cudaFuncAttributeMaxDynamicSharedMemorySize, SMEM_TOTAL);

    QWArgs qa;
    for (int c = 0; c < 2; c++) {
        for (int s = 0; s < 4; s++) qa.W[c*4 + s] = w[c][s];
        qa.b4[c] = bb[c][3];
        qa.H[c*4 + 0] = w1h + c*512*128; qa.L8[c*4 + 0] = w1l + c*512*128; qa.S[c*4 + 0] = ws1 + c*512;
        qa.H[c*4 + 1] = w2h + c*512*512; qa.L8[c*4 + 1] = w2l + c*512*512; qa.S[c*4 + 1] = ws2 + c*512;
        qa.H[c*4 + 2] = w3h + c*512*512; qa.L8[c*4 + 2] = w3l + c*512*512; qa.S[c*4 + 2] = ws3 + c*512;
        qa.H[c*4 + 3] = w4h + c*768*512; qa.L8[c*4 + 3] = w4l + c*768*512; qa.S[c*4 + 3] = ws4 + c*768;
        qa.bp[c] = b4p + c*768;
    }
    prep_all<<<(NS + 4608 + 7) / 8, 256>>>(qa, x, xq1h, xq1l, xs1);

    const dim3 gemmBlk(NTHR);
    const dim3 splineBlk(256);
    const int splineBlocks = (NS * 32) / 256;
    const int qactBlocks = NS / 8;
    const int nt512 = (NHID / BN) * (NS / BM);   // 4096
    const int nt768 = (NOUTP / BN) * (NS / BM);  // 6144

    for (int c = 0; c < 2; c++) {
        const int8_t* inH = (c == 0) ? xq1h : xq2h;
        const int8_t* inL = (c == 0) ? xq1l : xq2l;
        const float*  inS = (c == 0) ? xs1  : xs2;

        gemm_i8<1,1><<<GPERS, gemmBlk, SMEM_TOTAL>>>(inH, inL, inS,
            w1h + c*512*128, w1l + c*512*128, ws1 + c*512, bb[c][0], actF, NHID,
            NHID / BN, nt512);
        qact<4><<<qactBlocks, 256>>>(actF, NHID, NHID, q0h, q0l, s0);

        gemm_i8<4,1><<<GPERS, gemmBlk, SMEM_TOTAL>>>(q0h, q0l, s0,
            w2h + c*512*512, w2l + c*512*512, ws2 + c*512, bb[c][1], actF, NHID,
            NHID / BN, nt512);
        qact<4><<<qactBlocks, 256>>>(actF, NHID, NHID, q0h, q0l, s0);

        gemm_i8<4,1><<<GPERS, gemmBlk, SMEM_TOTAL>>>(q0h, q0l, s0,
            w3h + c*512*512, w3l + c*512*512, ws3 + c*512, bb[c][2], actF, NHID,
            NHID / BN, nt512);
        qact<4><<<qactBlocks, 256>>>(actF, NHID, NHID, q0h, q0l, s0);

        gemm_i8<4,0><<<GPERS, gemmBlk, SMEM_TOTAL>>>(q0h, q0l, s0,
            w4h + c*768*512, w4l + c*768*512, ws4 + c*768, b4p + c*768, bufC, NOUTP,
            NOUTP / BN, nt768);

        if (c == 0)
            spline_kernel<<<splineBlocks, splineBlk>>>(x + HALF, 64, bufC,
                out + HALF, 64, logdet, 0, xq2h, xq2l, xs2);
        else
            spline_kernel<<<splineBlocks, splineBlk>>>(x, 64, bufC,
                out, 64, logdet, 1, nullptr, nullptr, nullptr);
    }
}

// round 16
// speedup vs baseline: 1.0688x; 1.0688x over previous
#include <cuda_runtime.h>
#include <cstdint>

#define NS      65536
#define HALF    32
#define NHID    512
#define NOUT    736
#define NOUTP   768
#define KB      8
#define TB      3.0f

#define BM      128
#define BN      64
#define BKB     128
#define NTHR    128

#define SAH     0
#define SAL     16384
#define SBH     32768
#define SBL     40960
#define STAGE   49152
#define SMEM_TOTAL (2*STAGE)

// ================= static scratch =================
__device__ int8_t g_xq1h[(size_t)NS*128], g_xq1l[(size_t)NS*128];
__device__ float  g_xs1[NS];
__device__ int8_t g_xq2h[(size_t)NS*128], g_xq2l[(size_t)NS*128];
__device__ float  g_xs2[NS];
__device__ int8_t g_q0h[(size_t)NS*512],  g_q0l[(size_t)NS*512];
__device__ float  g_s0[NS];
__device__ float  g_act[(size_t)NS*512];
__device__ float  g_bufC[(size_t)NS*NOUTP];
__device__ int8_t g_w1h[2][512*128], g_w1l[2][512*128];
__device__ int8_t g_w2h[2][512*512], g_w2l[2][512*512];
__device__ int8_t g_w3h[2][512*512], g_w3l[2][512*512];
__device__ int8_t g_w4h[2][768*512], g_w4l[2][768*512];
__device__ float  g_ws1[2][512], g_ws2[2][512], g_ws3[2][512], g_ws4[2][768];
__device__ float  g_b4p[2][768];

// ================= helpers =================
__device__ __forceinline__ uint32_t smem_u32(const void* p) {
    uint32_t a;
    asm("{ .reg .u64 t; cvta.to.shared.u64 t, %1; cvt.u32.u64 %0, t; }" : "=r"(a) : "l"(p));
    return a;
}
#define SWZ(x) ((x) ^ (((x) >> 3) & 0x70))

#define CP16(dst, src) asm volatile("cp.async.cg.shared.global [%0], [%1], 16;" :: "r"(dst), "l"(src))
#define CP_COMMIT()    asm volatile("cp.async.commit_group;" ::: "memory")
#define CP_WAIT(N)     asm volatile("cp.async.wait_group %0;" :: "n"(N) : "memory")

#define LDSM4(r, a) \
    asm volatile("ldmatrix.sync.aligned.m8n8.x4.shared.b16 {%0,%1,%2,%3}, [%4];" \
        : "=r"((r)[0]), "=r"((r)[1]), "=r"((r)[2]), "=r"((r)[3]) : "r"(a))

#define MMAI8(c, a, b0, b1) \
    asm volatile("mma.sync.aligned.m16n8k32.row.col.s32.s8.s8.s32 " \
        "{%0,%1,%2,%3}, {%4,%5,%6,%7}, {%8,%9}, {%0,%1,%2,%3};" \
        : "+r"((c)[0]), "+r"((c)[1]), "+r"((c)[2]), "+r"((c)[3]) \
        : "r"((a)[0]), "r"((a)[1]), "r"((a)[2]), "r"((a)[3]), "r"(b0), "r"(b1))

// ================= int8 split GEMM (R14 structure; NKSL = active k32 slices) =================
template <int KT, int NKSL, int ACT>
__global__ void __launch_bounds__(NTHR, 2) gemm_i8(
    const int8_t* __restrict__ Aq, const int8_t* __restrict__ Aql,
    const float* __restrict__ sA,
    const int8_t* __restrict__ Bq, const int8_t* __restrict__ Bql,
    const float* __restrict__ sB,
    const float* __restrict__ bias,
    float* __restrict__ C, int ldc)
{
    extern __shared__ __align__(1024) char smem[];
    const uint32_t sb_ = smem_u32(smem);
    const int tid  = threadIdx.x;
    const int wid  = tid >> 5;
    const int l    = tid & 31;
    const int wm   = wid & 1;
    const int wn   = wid >> 1;
    const int row0 = blockIdx.y * BM;
    const int col0 = blockIdx.x * BN;
    const int lda  = KT * BKB;

    int acc1[4][4][4], acc2[4][4][4];
#pragma unroll
    for (int i = 0; i < 4; i++)
#pragma unroll
        for (int j = 0; j < 4; j++)
#pragma unroll
            for (int q = 0; q < 4; q++) { acc1[i][j][q] = 0; acc2[i][j][q] = 0; }

    auto load_tile = [&](int s, int m) {
        const uint32_t sbase = sb_ + s * STAGE;
        const int koff = m * BKB;
#pragma unroll
        for (int i = 0; i < 8; i++) {
            int c = tid + i * NTHR;
            int r = c >> 3, q = c & 7;
            uint32_t off = SWZ(r * 128 + q * 16);
            const size_t ga = (size_t)(row0 + r) * lda + koff + q * 16;
            CP16(sbase + SAH + off, Aq + ga);
            CP16(sbase + SAL + off, Aql + ga);
        }
#pragma unroll
        for (int i = 0; i < 4; i++) {
            int c = tid + i * NTHR;
            int n = c >> 3, q = c & 7;
            uint32_t off = SWZ(n * 128 + q * 16);
            const size_t gb = (size_t)(col0 + n) * lda + koff + q * 16;
            CP16(sbase + SBH + off, Bq + gb);
            CP16(sbase + SBL + off, Bql + gb);
        }
    };

    auto compute = [&](int s) {
        const uint32_t AHB = sb_ + s * STAGE + SAH;
        const uint32_t ALB = sb_ + s * STAGE + SAL;
        const uint32_t BHB = sb_ + s * STAGE + SBH;
        const uint32_t BLB = sb_ + s * STAGE + SBL;
#pragma unroll
        for (int ksl = 0; ksl < NKSL; ksl++) {
            uint32_t ah[4][4], al[4][4], bh[2][4], bl[2][4];
#pragma unroll
            for (int j16 = 0; j16 < 2; j16++) {
                int n = wn * 32 + j16 * 16 + (l & 7) + ((l >> 4) << 3);
                int colb = ksl * 32 + ((l >> 3) & 1) * 16;
                uint32_t sw = (uint32_t)((n & 7) << 4);
                LDSM4(bh[j16], BHB + n * 128 + (colb ^ sw));
                LDSM4(bl[j16], BLB + n * 128 + (colb ^ sw));
            }
#pragma unroll
            for (int i = 0; i < 4; i++) {
                int row = wm * 64 + i * 16 + (l & 15);
                int colb = ksl * 32 + (l >> 4) * 16;
                uint32_t sw = (uint32_t)((row & 7) << 4);
                LDSM4(ah[i], AHB + row * 128 + (colb ^ sw));
                LDSM4(al[i], ALB + row * 128 + (colb ^ sw));
            }
#pragma unroll
            for (int i = 0; i < 4; i++)
#pragma unroll
                for (int j16 = 0; j16 < 2; j16++)
#pragma unroll
                    for (int hf = 0; hf < 2; hf++)
                        MMAI8(acc1[i][j16 * 2 + hf], ah[i], bh[j16][hf*2], bh[j16][hf*2+1]);
#pragma unroll
            for (int i = 0; i < 4; i++)
#pragma unroll
                for (int j16 = 0; j16 < 2; j16++)
#pragma unroll
                    for (int hf = 0; hf < 2; hf++)
                        MMAI8(acc2[i][j16 * 2 + hf], ah[i], bl[j16][hf*2], bl[j16][hf*2+1]);
#pragma unroll
            for (int i = 0; i < 4; i++)
#pragma unroll
                for (int j16 = 0; j16 < 2; j16++)
#pragma unroll
                    for (int hf = 0; hf < 2; hf++)
                        MMAI8(acc2[i][j16 * 2 + hf], al[i], bh[j16][hf*2], bh[j16][hf*2+1]);
        }
    };

    load_tile(0, 0); CP_COMMIT();
#pragma unroll
    for (int kt = 0; kt < KT; kt++) {
        CP_WAIT(0);
        __syncthreads();
        if (kt + 1 < KT) { load_tile((kt + 1) & 1, kt + 1); CP_COMMIT(); }
        compute(kt & 1);
    }

#pragma unroll
    for (int i = 0; i < 4; i++) {
        const int r0 = row0 + wm * 64 + i * 16 + (l >> 2);
        const float sa0 = sA[r0], sa1 = sA[r0 + 8];
#pragma unroll
        for (int j = 0; j < 4; j++) {
            const int c = col0 + wn * 32 + j * 8 + (l & 3) * 2;
            const float sb0 = sB[c], sb1 = sB[c + 1];
            const float b0 = bias[c], b1 = bias[c + 1];
            float f0 = fmaf((float)acc1[i][j][0], 16384.f, (float)acc2[i][j][0] * 128.f);
            float f1 = fmaf((float)acc1[i][j][1], 16384.f, (float)acc2[i][j][1] * 128.f);
            float f2 = fmaf((float)acc1[i][j][2], 16384.f, (float)acc2[i][j][2] * 128.f);
            float f3 = fmaf((float)acc1[i][j][3], 16384.f, (float)acc2[i][j][3] * 128.f);
            float v0 = fmaf(f0, sa0 * sb0, b0);
            float v1 = fmaf(f1, sa0 * sb1, b1);
            float v2 = fmaf(f2, sa1 * sb0, b0);
            float v3 = fmaf(f3, sa1 * sb1, b1);
            if (ACT) {
                v0 = (v0 > 0.f) ? v0 : 0.2f * v0;
                v1 = (v1 > 0.f) ? v1 : 0.2f * v1;
                v2 = (v2 > 0.f) ? v2 : 0.2f * v2;
                v3 = (v3 > 0.f) ? v3 : 0.2f * v3;
            }
            *(float2*)(C + (size_t)r0 * ldc + c)       = make_float2(v0, v1);
            *(float2*)(C + (size_t)(r0 + 8) * ldc + c) = make_float2(v2, v3);
        }
    }
}

// ================= quant helpers =================
__device__ __forceinline__ void quant1(float v, float inv, float sa128,
                                       int8_t& h8, int8_t& l8) {
    int h = __float2int_rn(v * inv * (1.f / 128.f));
    float r = fmaf(-(float)h, sa128, v);
    int lo = __float2int_rn(r * inv);
    h8 = (int8_t)h; l8 = (int8_t)lo;
}

template <int NG>
__global__ void qact(const float* __restrict__ in, int inld, int ncols,
                     int8_t* __restrict__ qh, int8_t* __restrict__ ql,
                     float* __restrict__ scale)
{
    const int warp = (blockIdx.x * blockDim.x + threadIdx.x) >> 5;
    const int lane = threadIdx.x & 31;
    if (warp >= NS) return;
    const float* rp = in + (size_t)warp * inld;
    float4 v[NG];
    float amax = 0.f;
#pragma unroll
    for (int g = 0; g < NG; g++) {
        int c = g * 128 + lane * 4;
        v[g] = (c < ncols) ? *(const float4*)(rp + c) : make_float4(0.f, 0.f, 0.f, 0.f);
        amax = fmaxf(amax, fmaxf(fmaxf(fabsf(v[g].x), fabsf(v[g].y)),
                                 fmaxf(fabsf(v[g].z), fabsf(v[g].w))));
    }
#pragma unroll
    for (int off = 16; off > 0; off >>= 1)
        amax = fmaxf(amax, __shfl_xor_sync(0xffffffffu, amax, off));
    amax = fmaxf(amax, 1e-20f);
    const float sa    = amax * (1.f / 16256.f);
    const float inv   = 16256.f / amax;
    const float sa128 = sa * 128.f;
    const size_t base = (size_t)warp * (NG * 128);
#pragma unroll
    for (int g = 0; g < NG; g++) {
        int c = g * 128 + lane * 4;
        char4 h4, l4;
        quant1(v[g].x, inv, sa128, (int8_t&)h4.x, (int8_t&)l4.x);
        quant1(v[g].y, inv, sa128, (int8_t&)h4.y, (int8_t&)l4.y);
        quant1(v[g].z, inv, sa128, (int8_t&)h4.z, (int8_t&)l4.z);
        quant1(v[g].w, inv, sa128, (int8_t&)h4.w, (int8_t&)l4.w);
        *(char4*)(qh + base + c) = h4;
        *(char4*)(ql + base + c) = l4;
    }
    if (lane == 0) scale[warp] = sa;
}

// ================= merged prep =================
struct QWArgs {
    const float* W[8];
    const float* b4[2];
    int8_t* H[8];
    int8_t* L8[8];
    float*  S[8];
    float*  bp[2];
};

__global__ void prep_all(QWArgs a, const float* __restrict__ x,
                         int8_t* __restrict__ xqh, int8_t* __restrict__ xql,
                         float* __restrict__ xs)
{
    int gw = (int)((blockIdx.x * blockDim.x + threadIdx.x) >> 5);
    const int lane = threadIdx.x & 31;

    if (gw < NS) {
        const float* rp = x + (size_t)gw * 64;
        int c = lane * 4;
        float4 v = (c < HALF) ? *(const float4*)(rp + c) : make_float4(0.f, 0.f, 0.f, 0.f);
        float amax = fmaxf(fmaxf(fabsf(v.x), fabsf(v.y)), fmaxf(fabsf(v.z), fabsf(v.w)));
#pragma unroll
        for (int off = 16; off > 0; off >>= 1)
            amax = fmaxf(amax, __shfl_xor_sync(0xffffffffu, amax, off));
        amax = fmaxf(amax, 1e-20f);
        const float sa    = amax * (1.f / 16256.f);
        const float inv   = 16256.f / amax;
        const float sa128 = sa * 128.f;
        char4 h4, l4;
        quant1(v.x, inv, sa128, (int8_t&)h4.x, (int8_t&)l4.x);
        quant1(v.y, inv, sa128, (int8_t&)h4.y, (int8_t&)l4.y);
        quant1(v.z, inv, sa128, (int8_t&)h4.z, (int8_t&)l4.z);
        quant1(v.w, inv, sa128, (int8_t&)h4.w, (int8_t&)l4.w);
        const size_t base = (size_t)gw * 128 + c;
        *(char4*)(xqh + base) = h4;
        *(char4*)(xql + base) = l4;
        if (lane == 0) xs[gw] = sa;
        return;
    }
    gw -= NS;
    if (gw >= 4608) return;
    const int cc = (gw >= 2304) ? 1 : 0;
    int off = gw - cc * 2304;
    int seg, n, K, N, Kpad;
    if (off < 512)       { seg = 0; n = off;        K = 32;  N = 512; Kpad = 128; }
    else if (off < 1024) { seg = 1; n = off - 512;  K = 512; N = 512; Kpad = 512; }
    else if (off < 1536) { seg = 2; n = off - 1024; K = 512; N = 512; Kpad = 512; }
    else                 { seg = 3; n = off - 1536; K = 512; N = 736; Kpad = 512; }
    const int widx = cc * 4 + seg;
    const float* W = a.W[widx];
    const int nk = Kpad >> 5;

    float vals[16];
    float amax = 0.f;
#pragma unroll 16
    for (int i = 0; i < 16; i++) {
        if (i < nk) {
            int k = lane + 32 * i;
            float v = (k < K && n < N) ? W[(size_t)k * N + n] : 0.f;
            vals[i] = v;
            amax = fmaxf(amax, fabsf(v));
        }
    }
#pragma unroll
    for (int o = 16; o > 0; o >>= 1)
        amax = fmaxf(amax, __shfl_xor_sync(0xffffffffu, amax, o));
    amax = fmaxf(amax, 1e-20f);
    const float sbv   = amax * (1.f / 16256.f);
    const float inv   = 16256.f / amax;
    const float sb128 = sbv * 128.f;
    const size_t base = (size_t)n * Kpad;
#pragma unroll 16
    for (int i = 0; i < 16; i++) {
        if (i < nk) {
            int k = lane + 32 * i;
            int8_t h8, l8;
            quant1(vals[i], inv, sb128, h8, l8);
            a.H[widx][base + k]  = h8;
            a.L8[widx][base + k] = l8;
        }
    }
    if (lane == 0) {
        a.S[widx][n] = sbv;
        if (seg == 3) a.bp[cc][n] = (n < 736) ? a.b4[cc][n] : 0.f;
    }
}

// ================= spline (identical numerics) =================
__device__ __forceinline__ float softplusf(float x) {
    return (x > 0.f) ? (x + log1pf(expf(-x))) : log1pf(expf(x));
}

__global__ void __launch_bounds__(256) spline_kernel(
    const float* __restrict__ y, int ldy,
    const float* __restrict__ cond,
    float* __restrict__ out_y, int ldo,
    float* __restrict__ logdet, int add,
    int8_t* __restrict__ qh, int8_t* __restrict__ ql, float* __restrict__ qs)
{
    const int gid = blockIdx.x * 256 + threadIdx.x;
    const int s   = gid >> 5;
    const int dim = gid & 31;
    if (s >= NS) return;

    const float* p = cond + (size_t)s * NOUTP + dim * 23;
    const float x = y[(size_t)s * ldy + dim];

    float rw[KB], rh[KB];
#pragma unroll
    for (int i = 0; i < KB; i++) rw[i] = p[i];
#pragma unroll
    for (int i = 0; i < KB; i++) rh[i] = p[KB + i];

    float cw[KB + 1], wid[KB];
    {
        float m = rw[0];
#pragma unroll
        for (int i = 1; i < KB; i++) m = fmaxf(m, rw[i]);
        float s1 = 0.f, e[KB];
#pragma unroll
        for (int i = 0; i < KB; i++) { e[i] = expf(rw[i] - m); s1 += e[i]; }
        float inv1 = 1.f / s1, Wv[KB];
#pragma unroll
        for (int i = 0; i < KB; i++) Wv[i] = 2.f * TB * e[i] * inv1;
        float m2 = Wv[0];
#pragma unroll
        for (int i = 1; i < KB; i++) m2 = fmaxf(m2, Wv[i]);
        float s2 = 0.f;
#pragma unroll
        for (int i = 0; i < KB; i++) { e[i] = expf(Wv[i] - m2); s2 += e[i]; }
        float inv2 = 1.f / s2;
        float run = 0.f;
        cw[0] = -TB;
#pragma unroll
        for (int i = 0; i < KB; i++) {
            float w = 0.001f + (1.f - 0.001f * KB) * e[i] * inv2;
            run += w;
            cw[i + 1] = 2.f * TB * run - TB;
        }
        cw[KB] = TB;
#pragma unroll
        for (int i = 0; i < KB; i++) wid[i] = cw[i + 1] - cw[i];
    }

    float ch[KB + 1], hei[KB];
    {
        float m = rh[0];
#pragma unroll
        for (int i = 1; i < KB; i++) m = fmaxf(m, rh[i]);
        float s1 = 0.f, e[KB];
#pragma unroll
        for (int i = 0; i < KB; i++) { e[i] = expf(rh[i] - m); s1 += e[i]; }
        float inv1 = 1.f / s1, Hv[KB];
#pragma unroll
        for (int i = 0; i < KB; i++) Hv[i] = 2.f * TB * e[i] * inv1;
        float m2 = Hv[0];
#pragma unroll
        for (int i = 1; i < KB; i++) m2 = fmaxf(m2, Hv[i]);
        float s2 = 0.f;
#pragma unroll
        for (int i = 0; i < KB; i++) { e[i] = expf(Hv[i] - m2); s2 += e[i]; }
        float inv2 = 1.f / s2;
        float run = 0.f;
        ch[0] = -TB;
#pragma unroll
        for (int i = 0; i < KB; i++) {
            float h = 0.001f + (1.f - 0.001f * KB) * e[i] * inv2;
            run += h;
            ch[i + 1] = 2.f * TB * run - TB;
        }
        ch[KB] = TB;
#pragma unroll
        for (int i = 0; i < KB; i++) hei[i] = ch[i + 1] - ch[i];
    }

    float der[KB + 1];
    {
        const float CONST = 0.5397432446f;
        der[0] = 0.001f + softplusf(CONST);
        der[KB] = der[0];
#pragma unroll
        for (int i = 0; i < KB - 1; i++)
            der[i + 1] = 0.001f + softplusf(softplusf(p[2 * KB + i]));
    }

    const bool inside = (x >= -TB) && (x <= TB);
    const float xc = fminf(fmaxf(x, -TB), TB);
    int cnt = 0;
#pragma unroll
    for (int j = 0; j <= KB; j++) {
        float ce = cw[j] + ((j == KB) ? 1e-6f : 0.f);
        cnt += (xc >= ce) ? 1 : 0;
    }
    int idx = min(max(cnt - 1, 0), KB - 1);

    float in_cw = 0.f, in_w = 1.f, in_ch = 0.f, in_h = 1.f, in_der = 1.f, in_der1 = 1.f;
#pragma unroll
    for (int j = 0; j < KB; j++) {
        if (j == idx) {
            in_cw = cw[j]; in_w = wid[j]; in_ch = ch[j]; in_h = hei[j];
            in_der = der[j]; in_der1 = der[j + 1];
        }
    }
    const float in_d = in_h / in_w;
    const float theta = (xc - in_cw) / in_w;
    const float t1mt  = theta * (1.f - theta);
    const float num   = in_h * (in_d * theta * theta + in_der * t1mt);
    const float den   = in_d + (in_der + in_der1 - 2.f * in_d) * t1mt;
    const float outv  = in_ch + num / den;
    const float omt   = 1.f - theta;
    const float dnum  = in_d * in_d * (in_der1 * theta * theta + 2.f * in_d * t1mt + in_der * omt * omt);
    float lad = logf(dnum) - 2.f * logf(den);

    const float fv = inside ? outv : x;
    out_y[(size_t)s * ldo + dim] = fv;
    lad = inside ? lad : 0.f;

    if (qh) {
        float amax = fabsf(fv);
#pragma unroll
        for (int off = 16; off > 0; off >>= 1)
            amax = fmaxf(amax, __shfl_xor_sync(0xffffffffu, amax, off));
        amax = fmaxf(amax, 1e-20f);
        const float sa    = amax * (1.f / 16256.f);
        const float inv   = 16256.f / amax;
        const float sa128 = sa * 128.f;
        int8_t h8, l8;
        quant1(fv, inv, sa128, h8, l8);
        const size_t base = (size_t)s * 128 + dim;
        qh[base] = h8;  ql[base] = l8;
        qh[base + 32] = 0; ql[base + 32] = 0;
        qh[base + 64] = 0; ql[base + 64] = 0;
        qh[base + 96] = 0; ql[base + 96] = 0;
        if (dim == 0) qs[s] = sa;
    }

#pragma unroll
    for (int off = 16; off > 0; off >>= 1)
        lad += __shfl_down_sync(0xffffffffu, lad, off);
    if (dim == 0) {
        if (add) logdet[s] += lad;
        else     logdet[s]  = lad;
    }
}

// ================= launch =================
extern "C" void kernel_launch(void* const* d_in, const int* in_sizes, int n_in,
                              void* d_out, int out_size)
{
    const float* x = (const float*)d_in[0];
    const float* w[2][4] = {{(const float*)d_in[1], (const float*)d_in[3], (const float*)d_in[5], (const float*)d_in[7]},
                            {(const float*)d_in[9], (const float*)d_in[11], (const float*)d_in[13], (const float*)d_in[15]}};
    const float* bb[2][4] = {{(const float*)d_in[2], (const float*)d_in[4], (const float*)d_in[6], (const float*)d_in[8]},
                             {(const float*)d_in[10], (const float*)d_in[12], (const float*)d_in[14], (const float*)d_in[16]}};

    float* out    = (float*)d_out;
    float* logdet = out + (size_t)NS * 64;

    int8_t *xq1h, *xq1l, *xq2h, *xq2l, *q0h, *q0l;
    float  *xs1, *xs2, *s0, *actF, *bufC, *b4p;
    int8_t *w1h, *w1l, *w2h, *w2l, *w3h, *w3l, *w4h, *w4l;
    float  *ws1, *ws2, *ws3, *ws4;
    cudaGetSymbolAddress((void**)&xq1h, g_xq1h); cudaGetSymbolAddress((void**)&xq1l, g_xq1l);
    cudaGetSymbolAddress((void**)&xs1, g_xs1);
    cudaGetSymbolAddress((void**)&xq2h, g_xq2h); cudaGetSymbolAddress((void**)&xq2l, g_xq2l);
    cudaGetSymbolAddress((void**)&xs2, g_xs2);
    cudaGetSymbolAddress((void**)&q0h, g_q0h);   cudaGetSymbolAddress((void**)&q0l, g_q0l);
    cudaGetSymbolAddress((void**)&s0, g_s0);
    cudaGetSymbolAddress((void**)&actF, g_act);
    cudaGetSymbolAddress((void**)&bufC, g_bufC);
    cudaGetSymbolAddress((void**)&w1h, g_w1h); cudaGetSymbolAddress((void**)&w1l, g_w1l);
    cudaGetSymbolAddress((void**)&w2h, g_w2h); cudaGetSymbolAddress((void**)&w2l, g_w2l);
    cudaGetSymbolAddress((void**)&w3h, g_w3h); cudaGetSymbolAddress((void**)&w3l, g_w3l);
    cudaGetSymbolAddress((void**)&w4h, g_w4h); cudaGetSymbolAddress((void**)&w4l, g_w4l);
    cudaGetSymbolAddress((void**)&ws1, g_ws1); cudaGetSymbolAddress((void**)&ws2, g_ws2);
    cudaGetSymbolAddress((void**)&ws3, g_ws3); cudaGetSymbolAddress((void**)&ws4, g_ws4);
    cudaGetSymbolAddress((void**)&b4p, g_b4p);

    cudaFuncSetAttribute(gemm_i8<1,1,1>, cudaFuncAttributeMaxDynamicSharedMemorySize, SMEM_TOTAL);
    cudaFuncSetAttribute(gemm_i8<4,4,1>, cudaFuncAttributeMaxDynamicSharedMemorySize, SMEM_TOTAL);
    cudaFuncSetAttribute(gemm_i8<4,4,0>, cudaFuncAttributeMaxDynamicSharedMemorySize, SMEM_TOTAL);

    QWArgs qa;
    for (int c = 0; c < 2; c++) {
        for (int s = 0; s < 4; s++) qa.W[c*4 + s] = w[c][s];
        qa.b4[c] = bb[c][3];
        qa.H[c*4 + 0] = w1h + c*512*128; qa.L8[c*4 + 0] = w1l + c*512*128; qa.S[c*4 + 0] = ws1 + c*512;
        qa.H[c*4 + 1] = w2h + c*512*512; qa.L8[c*4 + 1] = w2l + c*512*512; qa.S[c*4 + 1] = ws2 + c*512;
        qa.H[c*4 + 2] = w3h + c*512*512; qa.L8[c*4 + 2] = w3l + c*512*512; qa.S[c*4 + 2] = ws3 + c*512;
        qa.H[c*4 + 3] = w4h + c*768*512; qa.L8[c*4 + 3] = w4l + c*768*512; qa.S[c*4 + 3] = ws4 + c*768;
        qa.bp[c] = b4p + c*768;
    }
    prep_all<<<(NS + 4608 + 7) / 8, 256>>>(qa, x, xq1h, xq1l, xs1);

    const dim3 gemmBlk(NTHR);
    const dim3 g512(NHID / BN, NS / BM);     // (8, 512)
    const dim3 g768(NOUTP / BN, NS / BM);    // (12, 512)
    const dim3 splineBlk(256);
    const int splineBlocks = (NS * 32) / 256;
    const int qactBlocks = NS / 8;

    for (int c = 0; c < 2; c++) {
        const int8_t* inH = (c == 0) ? xq1h : xq2h;
        const int8_t* inL = (c == 0) ? xq1l : xq2l;
        const float*  inS = (c == 0) ? xs1  : xs2;

        gemm_i8<1,1,1><<<g512, gemmBlk, SMEM_TOTAL>>>(inH, inL, inS,
            w1h + c*512*128, w1l + c*512*128, ws1 + c*512, bb[c][0], actF, NHID);
        qact<4><<<qactBlocks, 256>>>(actF, NHID, NHID, q0h, q0l, s0);

        gemm_i8<4,4,1><<<g512, gemmBlk, SMEM_TOTAL>>>(q0h, q0l, s0,
            w2h + c*512*512, w2l + c*512*512, ws2 + c*512, bb[c][1], actF, NHID);
        qact<4><<<qactBlocks, 256>>>(actF, NHID, NHID, q0h, q0l, s0);

        gemm_i8<4,4,1><<<g512, gemmBlk, SMEM_TOTAL>>>(q0h, q0l, s0,
            w3h + c*512*512, w3l + c*512*512, ws3 + c*512, bb[c][2], actF, NHID);
        qact<4><<<qactBlocks, 256>>>(actF, NHID, NHID, q0h, q0l, s0);

        gemm_i8<4,4,0><<<g768, gemmBlk, SMEM_TOTAL>>>(q0h, q0l, s0,
            w4h + c*768*512, w4l + c*768*512, ws4 + c*768, b4p + c*768, bufC, NOUTP);

        if (c == 0)
            spline_kernel<<<splineBlocks, splineBlk>>>(x + HALF, 64, bufC,
                out + HALF, 64, logdet, 0, xq2h, xq2l, xs2);
        else
            spline_kernel<<<splineBlocks, splineBlk>>>(x, 64, bufC,
                out, 64, logdet, 1, nullptr, nullptr, nullptr);
    }
}